// round 13
// baseline (speedup 1.0000x reference)
#include <cuda_runtime.h>
#include <cuda_bf16.h>
#include <math.h>
#include <stdint.h>

#define B 1024
#define L 18
#define E 300
#define H 300
#define G4 1200
#define KP 304          // H padded to 16
#define NPAD 1280       // G4 padded to 160-tile
#define VS 2186
#define BL (B*L)
#define VROW 608        // packed Vh row length (2H padded to 16)

#define ABYTES 10240    // 128 rows * 80 B
#define BUFB   23040    // A(10240) + B(160*80=12800)
#define FFSMEM (4*BUFB)
#define PSMEM (4*8192 + 19*10240)   // 227328

// ---------------- scratch ----------------
__device__ float g_ag[B * E];
__device__ float g_w [B * E];
__device__ float g_sproj[2][VS * G4];     // interleaved cols n'=4j+gate
__device__ float g_wproj[2][B * G4];      // interleaved
__device__ uint32_t g_Vpk[BL * VROW];     // Vh packed (hi,lo) bf16x2
__device__ uint32_t g_hpk[2][2][B * KP];  // h packed (hi,lo) bf16x2 [dir][buf]
__device__ __nv_bfloat16 g_Whi[2][NPAD * KP];  // Whh permuted [n'][k] hi
__device__ __nv_bfloat16 g_Wlo[2][NPAD * KP];  // lo

// ---------------- helpers ----------------
__device__ __forceinline__ void spb(float v, float& hi, float& lo) {
    hi = __bfloat162float(__float2bfloat16(v));
    lo = v - hi;
}
__device__ __forceinline__ uint32_t pack2(float x, float y) {
    __nv_bfloat162 v = __floats2bfloat162_rn(x, y);
    return *reinterpret_cast<uint32_t*>(&v);
}
__device__ __forceinline__ void ldsm4(uint32_t* r, uint32_t addr) {
    asm volatile("ldmatrix.sync.aligned.m8n8.x4.shared.b16 {%0,%1,%2,%3}, [%4];"
        : "=r"(r[0]), "=r"(r[1]), "=r"(r[2]), "=r"(r[3]) : "r"(addr));
}
__device__ __forceinline__ void ldsm2(uint32_t& r0, uint32_t& r1, uint32_t addr) {
    asm volatile("ldmatrix.sync.aligned.m8n8.x2.shared.b16 {%0,%1}, [%2];"
        : "=r"(r0), "=r"(r1) : "r"(addr));
}
__device__ __forceinline__ void mma16(float* c, const uint32_t* a, const uint32_t* b) {
    asm volatile("mma.sync.aligned.m16n8k16.row.col.f32.bf16.bf16.f32 "
        "{%0,%1,%2,%3},{%4,%5,%6,%7},{%8,%9},{%0,%1,%2,%3};"
        : "+f"(c[0]), "+f"(c[1]), "+f"(c[2]), "+f"(c[3])
        : "r"(a[0]), "r"(a[1]), "r"(a[2]), "r"(a[3]), "r"(b[0]), "r"(b[1]));
}
__device__ __forceinline__ uint4 ldcg4(const void* p) {
    uint4 v;
    asm volatile("ld.global.cg.v4.u32 {%0,%1,%2,%3}, [%4];"
        : "=r"(v.x), "=r"(v.y), "=r"(v.z), "=r"(v.w) : "l"(p));
    return v;
}
__device__ __forceinline__ uint32_t swz(int row, int seg) {
    return (uint32_t)(row * 64 + (((seg + (row >> 1)) & 3) << 4));
}
__device__ __forceinline__ float sigf(float x) {
    return __fdividef(1.f, 1.f + __expf(-x));
}
__device__ __forceinline__ float tanhfast(float x) {
    float xc = fminf(fmaxf(x, -15.f), 15.f);
    float e = __expf(2.f * xc);
    return __fdividef(e - 1.f, e + 1.f);
}

// ---------------- mma chunk, warp tile 32x40, 80B-stride layout ----------------
__device__ __forceinline__ void mma_chunk80(uint32_t Ab, uint32_t Bb, int lane,
                                            int wm, int wn, float (&acc)[2][5][4]) {
    int r8 = lane & 7, sel = lane >> 3;
    int arow = ((sel & 1) << 3) + r8;
    int akoff = (sel >> 1) << 4;
    uint32_t ah[2][4], al[2][4];
#pragma unroll
    for (int im = 0; im < 2; im++) {
        uint32_t addr = Ab + (uint32_t)((wm + im * 16 + arow) * 80 + akoff);
        ldsm4(ah[im], addr);
        ldsm4(al[im], addr + 32);
    }
    uint32_t bh[5][2], bl[5][2];
    int brow = ((sel >> 1) << 3) + r8;
    int bkoff = (sel & 1) << 4;
#pragma unroll
    for (int j2 = 0; j2 < 2; j2++) {
        uint32_t addr = Bb + (uint32_t)((wn + j2 * 16 + brow) * 80 + bkoff);
        uint32_t t[4];
        ldsm4(t, addr);
        bh[2 * j2][0] = t[0]; bh[2 * j2][1] = t[1];
        bh[2 * j2 + 1][0] = t[2]; bh[2 * j2 + 1][1] = t[3];
        ldsm4(t, addr + 32);
        bl[2 * j2][0] = t[0]; bl[2 * j2][1] = t[1];
        bl[2 * j2 + 1][0] = t[2]; bl[2 * j2 + 1][1] = t[3];
    }
    {
        int row2 = lane & 7;
        int koff2 = ((lane >> 3) & 1) << 4;
        uint32_t addr = Bb + (uint32_t)((wn + 32 + row2) * 80 + koff2);
        ldsm2(bh[4][0], bh[4][1], addr);
        ldsm2(bl[4][0], bl[4][1], addr + 32);
    }
#pragma unroll
    for (int n8 = 0; n8 < 5; n8++)
#pragma unroll
        for (int im = 0; im < 2; im++) {
            mma16(acc[im][n8], ah[im], bh[n8]);
            mma16(acc[im][n8], al[im], bh[n8]);
            mma16(acc[im][n8], ah[im], bl[n8]);
        }
}

// ---------------- mma chunk, warp tile 32x40, swizzled 64B layout ----------------
__device__ __forceinline__ void mma_chunk64(uint32_t Ab, uint32_t Bb, int lane,
                                            int wm, int wn, float (&acc)[2][5][4]) {
    int r8 = lane & 7, sel = lane >> 3;
    int arow = ((sel & 1) << 3) + r8;
    int akseg = sel >> 1;
    uint32_t ah[2][4], al[2][4];
#pragma unroll
    for (int im = 0; im < 2; im++) {
        int row = wm + im * 16 + arow;
        ldsm4(ah[im], Ab + swz(row, akseg));
        ldsm4(al[im], Ab + swz(row, akseg + 2));
    }
    uint32_t bh[5][2], bl[5][2];
    int brow = ((sel >> 1) << 3) + r8;
    int bkseg = sel & 1;
#pragma unroll
    for (int j2 = 0; j2 < 2; j2++) {
        int row = wn + j2 * 16 + brow;
        uint32_t t[4];
        ldsm4(t, Bb + swz(row, bkseg));
        bh[2 * j2][0] = t[0]; bh[2 * j2][1] = t[1];
        bh[2 * j2 + 1][0] = t[2]; bh[2 * j2 + 1][1] = t[3];
        ldsm4(t, Bb + swz(row, bkseg + 2));
        bl[2 * j2][0] = t[0]; bl[2 * j2][1] = t[1];
        bl[2 * j2 + 1][0] = t[2]; bl[2 * j2 + 1][1] = t[3];
    }
    {
        int row = wn + 32 + (lane & 7);
        int seg = (lane >> 3) & 1;
        ldsm2(bh[4][0], bh[4][1], Bb + swz(row, seg));
        ldsm2(bl[4][0], bl[4][1], Bb + swz(row, seg + 2));
    }
#pragma unroll
    for (int n8 = 0; n8 < 5; n8++)
#pragma unroll
        for (int im = 0; im < 2; im++) {
            mma16(acc[im][n8], ah[im], bh[n8]);
            mma16(acc[im][n8], al[im], bh[n8]);
            mma16(acc[im][n8], ah[im], bl[n8]);
        }
}

// ---------------- init ----------------
__global__ void init_kernel() {
    int i = blockIdx.x * blockDim.x + threadIdx.x;
    if (i < 2 * 2 * B * KP) (&g_hpk[0][0][0])[i] = 0u;
    if (i < BL * 8) {
        int row = i >> 3;
        g_Vpk[(size_t)row * VROW + 600 + (i & 7)] = 0u;
    }
}

__global__ void prep_whh(const float* __restrict__ Wf, const float* __restrict__ Wb) {
    int i = blockIdx.x * blockDim.x + threadIdx.x;
    if (i >= 2 * NPAD * KP) return;
    int dir = i / (NPAD * KP);
    int r = i - dir * (NPAD * KP);
    int np = r / KP, k = r - np * KP;
    float v = 0.f;
    if (np < G4 && k < H) {
        const float* W = dir ? Wb : Wf;
        v = W[(size_t)((np & 3) * H + (np >> 2)) * H + k];
    }
    float hi, lo; spb(v, hi, lo);
    g_Whi[dir][r] = __float2bfloat16(hi);
    g_Wlo[dir][r] = __float2bfloat16(lo);
}

__global__ void embed_kernel(const int* __restrict__ word,
                             const int* __restrict__ sem,
                             const float* __restrict__ wt,
                             const float* __restrict__ st) {
    int b = blockIdx.x;
    int e = threadIdx.x;
    __shared__ int sidx[L];
    __shared__ int widx;
    if (e < L) sidx[e] = sem[b * L + e];
    if (e == 0) widx = word[b];
    __syncthreads();
    if (e < E) {
        float acc = 0.f;
#pragma unroll
        for (int l = 0; l < L; l++) acc += st[sidx[l] * E + e];
        g_ag[b * E + e] = acc * (1.f / (float)L);
        g_w [b * E + e] = wt[widx * E + e];
    }
}

// ---------------- feed-forward gemm body (4-deep ring, sync per 2 chunks) ----------------
__device__ __forceinline__ void gemm_body(
    unsigned char* smraw,
    const float* A, int lda, const float* W, int ldw, int imap,
    const float* b1, const float* b2, float* C,
    int M, int N, int K, int dorelu, int bx, int by)
{
    uint32_t sbase = (uint32_t)__cvta_generic_to_shared(smraw);
    uint32_t* smw = (uint32_t*)smraw;

    int tid = threadIdx.x, lane = tid & 31, wid = tid >> 5;
    int g = lane >> 2, t4 = lane & 3;
    int wm = (wid >> 2) * 32, wn = (wid & 3) * 40;
    int m0 = by * 128, n0 = bx * 160;

    float acc[2][5][4];
#pragma unroll
    for (int a = 0; a < 2; a++)
#pragma unroll
        for (int b = 0; b < 5; b++)
#pragma unroll
            for (int c = 0; c < 4; c++) acc[a][b][c] = 0.f;

    int NC = (K + 15) / 16;
    int NG = (NC + 1) / 2;
    float4 ra[2], rb[2][2];

    auto loadregs = [&](int kc, int sl) {
        int k0 = kc * 16;
        {
            int row = tid >> 2, q4 = tid & 3;
            int gm = m0 + row, kk = k0 + q4 * 4;
            float4 v = make_float4(0.f, 0.f, 0.f, 0.f);
            if (gm < M) {
                const float* ap = A + (size_t)gm * lda;
                if (kk + 3 < K) v = *(const float4*)(ap + kk);
                else {
                    if (kk + 0 < K) v.x = ap[kk + 0];
                    if (kk + 1 < K) v.y = ap[kk + 1];
                    if (kk + 2 < K) v.z = ap[kk + 2];
                    if (kk + 3 < K) v.w = ap[kk + 3];
                }
            }
            ra[sl] = v;
        }
#pragma unroll
        for (int q = 0; q < 2; q++) {
            int p = tid + q * 512;
            float4 v = make_float4(0.f, 0.f, 0.f, 0.f);
            if (p < 640) {
                int row = p >> 2, q4 = p & 3;
                int nr = n0 + row, kk = k0 + q4 * 4;
                if (nr < N) {
                    int grow = imap ? ((nr & 3) * H + (nr >> 2)) : nr;
                    const float* wp = W + (size_t)grow * ldw;
                    if (kk + 3 < K) v = *(const float4*)(wp + kk);
                    else {
                        if (kk + 0 < K) v.x = wp[kk + 0];
                        if (kk + 1 < K) v.y = wp[kk + 1];
                        if (kk + 2 < K) v.z = wp[kk + 2];
                        if (kk + 3 < K) v.w = wp[kk + 3];
                    }
                }
            }
            rb[sl][q] = v;
        }
    };
    auto storeregs = [&](int sl, int buf) {
        uint32_t* Aw = smw + buf * (BUFB / 4);
        uint32_t* Bw = Aw + ABYTES / 4;
        {
            int row = tid >> 2, q4 = tid & 3;
            float h0, l0, h1, l1, h2, l2, h3, l3;
            spb(ra[sl].x, h0, l0); spb(ra[sl].y, h1, l1);
            spb(ra[sl].z, h2, l2); spb(ra[sl].w, h3, l3);
            Aw[row * 20 + q4 * 2]     = pack2(h0, h1);
            Aw[row * 20 + q4 * 2 + 1] = pack2(h2, h3);
            Aw[row * 20 + 8 + q4 * 2]     = pack2(l0, l1);
            Aw[row * 20 + 8 + q4 * 2 + 1] = pack2(l2, l3);
        }
#pragma unroll
        for (int q = 0; q < 2; q++) {
            int p = tid + q * 512;
            if (p < 640) {
                int row = p >> 2, q4 = p & 3;
                float h0, l0, h1, l1, h2, l2, h3, l3;
                spb(rb[sl][q].x, h0, l0); spb(rb[sl][q].y, h1, l1);
                spb(rb[sl][q].z, h2, l2); spb(rb[sl][q].w, h3, l3);
                Bw[row * 20 + q4 * 2]     = pack2(h0, h1);
                Bw[row * 20 + q4 * 2 + 1] = pack2(h2, h3);
                Bw[row * 20 + 8 + q4 * 2]     = pack2(l0, l1);
                Bw[row * 20 + 8 + q4 * 2 + 1] = pack2(l2, l3);
            }
        }
    };

    loadregs(0, 0);
    if (1 < NC) loadregs(1, 1);
    storeregs(0, 0);
    if (1 < NC) storeregs(1, 1);
    __syncthreads();
    for (int gg = 0; gg < NG; gg++) {
        int base2 = 2 * gg;
        if (gg + 1 < NG) {
            loadregs(base2 + 2, 0);
            if (base2 + 3 < NC) loadregs(base2 + 3, 1);
        }
        mma_chunk80(sbase + (uint32_t)((base2 & 3) * BUFB),
                    sbase + (uint32_t)((base2 & 3) * BUFB) + ABYTES, lane, wm, wn, acc);
        if (base2 + 1 < NC)
            mma_chunk80(sbase + (uint32_t)(((base2 + 1) & 3) * BUFB),
                        sbase + (uint32_t)(((base2 + 1) & 3) * BUFB) + ABYTES, lane, wm, wn, acc);
        if (gg + 1 < NG) {
            storeregs(0, (base2 + 2) & 3);
            if (base2 + 3 < NC) storeregs(1, (base2 + 3) & 3);
        }
        __syncthreads();
    }

#pragma unroll
    for (int in8 = 0; in8 < 5; in8++) {
        int n_g = n0 + wn + in8 * 8 + 2 * t4;
        float bv0 = 0.f, bv1 = 0.f;
        if (n_g < N) {
            int i0 = imap ? ((n_g & 3) * H + (n_g >> 2)) : n_g;
            if (b1) bv0 += b1[i0];
            if (b2) bv0 += b2[i0];
        }
        if (n_g + 1 < N) {
            int i1 = imap ? (((n_g + 1) & 3) * H + ((n_g + 1) >> 2)) : (n_g + 1);
            if (b1) bv1 += b1[i1];
            if (b2) bv1 += b2[i1];
        }
#pragma unroll
        for (int im = 0; im < 2; im++) {
            int r0 = m0 + wm + im * 16 + g;
            if (r0 < M) {
                if (n_g < N) {
                    float v = acc[im][in8][0] + bv0;
                    if (dorelu) v = fmaxf(v, 0.f);
                    C[(size_t)r0 * N + n_g] = v;
                }
                if (n_g + 1 < N) {
                    float v = acc[im][in8][1] + bv1;
                    if (dorelu) v = fmaxf(v, 0.f);
                    C[(size_t)r0 * N + n_g + 1] = v;
                }
            }
            int r1 = r0 + 8;
            if (r1 < M) {
                if (n_g < N) {
                    float v = acc[im][in8][2] + bv0;
                    if (dorelu) v = fmaxf(v, 0.f);
                    C[(size_t)r1 * N + n_g] = v;
                }
                if (n_g + 1 < N) {
                    float v = acc[im][in8][3] + bv1;
                    if (dorelu) v = fmaxf(v, 0.f);
                    C[(size_t)r1 * N + n_g + 1] = v;
                }
            }
        }
    }
}

// ---------------- merged feed-forward launch ----------------
__global__ void __launch_bounds__(512) gemm_ff(
    const float* Wb_, const float* bb_, const float* st,
    const float* Wih_f, const float* Wih_b,
    const float* bih_f, const float* bhh_f,
    const float* bih_b, const float* bhh_b,
    float* vg_out, float* psf, float* psb, float* pwf, float* pwb)
{
    extern __shared__ __align__(16) unsigned char smdyn[];
    int bid = blockIdx.x;
    if (bid < 16) {
        gemm_body(smdyn, g_ag, E, Wb_, E, 0, bb_, nullptr, vg_out,
                  B, E, E, 1, bid & 1, bid >> 1);
    } else if (bid < 160) {
        int r = bid - 16;
        gemm_body(smdyn, st, E, Wih_f + E, 2 * E, 1, bih_f, bhh_f, psf,
                  VS, G4, E, 0, r & 7, r >> 3);
    } else if (bid < 304) {
        int r = bid - 160;
        gemm_body(smdyn, st, E, Wih_b + E, 2 * E, 1, bih_b, bhh_b, psb,
                  VS, G4, E, 0, r & 7, r >> 3);
    } else if (bid < 368) {
        int r = bid - 304;
        gemm_body(smdyn, g_w, E, Wih_f, 2 * E, 1, nullptr, nullptr, pwf,
                  B, G4, E, 0, r & 7, r >> 3);
    } else {
        int r = bid - 368;
        gemm_body(smdyn, g_w, E, Wih_b, 2 * E, 1, nullptr, nullptr, pwb,
                  B, G4, E, 0, r & 7, r >> 3);
    }
}

// ---------------- final V gemm: packed bf16x2 A operand ----------------
__global__ void __launch_bounds__(512) gemm_v(const float* Wa, const float* ba,
                                              float* Vout)
{
    extern __shared__ __align__(16) unsigned char smdyn[];
    uint32_t sbase = (uint32_t)__cvta_generic_to_shared(smdyn);
    uint32_t* smw = (uint32_t*)smdyn;

    int tid = threadIdx.x, lane = tid & 31, wid = tid >> 5;
    int g = lane >> 2, t4 = lane & 3;
    int wm = (wid >> 2) * 32, wn = (wid & 3) * 40;
    int m0 = blockIdx.y * 128, n0 = blockIdx.x * 160;
    const int M = BL, N = H, K = 2 * H;
    const int NC = 38, NG = 19;

    float acc[2][5][4];
#pragma unroll
    for (int a = 0; a < 2; a++)
#pragma unroll
        for (int b = 0; b < 5; b++)
#pragma unroll
            for (int c = 0; c < 4; c++) acc[a][b][c] = 0.f;

    int arow = tid >> 2, akq = tid & 3;
    uint4 ua[2];
    float4 rb[2][2];

    auto loadregs = [&](int kc, int sl) {
        ua[sl] = *(const uint4*)(g_Vpk + (size_t)(m0 + arow) * VROW + kc * 16 + akq * 4);
        int k0 = kc * 16;
#pragma unroll
        for (int q = 0; q < 2; q++) {
            int p = tid + q * 512;
            float4 v = make_float4(0.f, 0.f, 0.f, 0.f);
            if (p < 640) {
                int row = p >> 2, q4 = p & 3;
                int nr = n0 + row, kk = k0 + q4 * 4;
                if (nr < N) {
                    const float* wp = Wa + (size_t)nr * K;
                    if (kk + 3 < K) v = *(const float4*)(wp + kk);
                    else {
                        if (kk + 0 < K) v.x = wp[kk + 0];
                        if (kk + 1 < K) v.y = wp[kk + 1];
                        if (kk + 2 < K) v.z = wp[kk + 2];
                        if (kk + 3 < K) v.w = wp[kk + 3];
                    }
                }
            }
            rb[sl][q] = v;
        }
    };
    auto storeregs = [&](int sl, int buf) {
        uint32_t* Aw = smw + buf * (BUFB / 4);
        uint32_t* Bw = Aw + ABYTES / 4;
        {
            uint4 u = ua[sl];
            Aw[arow * 20 + akq * 2]     = __byte_perm(u.x, u.y, 0x5410);
            Aw[arow * 20 + akq * 2 + 1] = __byte_perm(u.z, u.w, 0x5410);
            Aw[arow * 20 + 8 + akq * 2]     = __byte_perm(u.x, u.y, 0x7632);
            Aw[arow * 20 + 8 + akq * 2 + 1] = __byte_perm(u.z, u.w, 0x7632);
        }
#pragma unroll
        for (int q = 0; q < 2; q++) {
            int p = tid + q * 512;
            if (p < 640) {
                int row = p >> 2, q4 = p & 3;
                float h0, l0, h1, l1, h2, l2, h3, l3;
                spb(rb[sl][q].x, h0, l0); spb(rb[sl][q].y, h1, l1);
                spb(rb[sl][q].z, h2, l2); spb(rb[sl][q].w, h3, l3);
                Bw[row * 20 + q4 * 2]     = pack2(h0, h1);
                Bw[row * 20 + q4 * 2 + 1] = pack2(h2, h3);
                Bw[row * 20 + 8 + q4 * 2]     = pack2(l0, l1);
                Bw[row * 20 + 8 + q4 * 2 + 1] = pack2(l2, l3);
            }
        }
    };

    loadregs(0, 0);
    loadregs(1, 1);
    storeregs(0, 0);
    storeregs(1, 1);
    __syncthreads();
    for (int gg = 0; gg < NG; gg++) {
        int base2 = 2 * gg;
        if (gg + 1 < NG) {
            loadregs(base2 + 2, 0);
            loadregs(base2 + 3, 1);
        }
        mma_chunk80(sbase + (uint32_t)((base2 & 3) * BUFB),
                    sbase + (uint32_t)((base2 & 3) * BUFB) + ABYTES, lane, wm, wn, acc);
        mma_chunk80(sbase + (uint32_t)(((base2 + 1) & 3) * BUFB),
                    sbase + (uint32_t)(((base2 + 1) & 3) * BUFB) + ABYTES, lane, wm, wn, acc);
        if (gg + 1 < NG) {
            storeregs(0, (base2 + 2) & 3);
            storeregs(1, (base2 + 3) & 3);
        }
        __syncthreads();
    }

#pragma unroll
    for (int in8 = 0; in8 < 5; in8++) {
        int n_g = n0 + wn + in8 * 8 + 2 * t4;
        float bv0 = (n_g < N) ? ba[n_g] : 0.f;
        float bv1 = (n_g + 1 < N) ? ba[n_g + 1] : 0.f;
#pragma unroll
        for (int im = 0; im < 2; im++) {
            int r0 = m0 + wm + im * 16 + g;
            if (n_g < N)
                Vout[(size_t)r0 * N + n_g] = fmaxf(acc[im][in8][0] + bv0, 0.f);
            if (n_g + 1 < N)
                Vout[(size_t)r0 * N + n_g + 1] = fmaxf(acc[im][in8][1] + bv1, 0.f);
            int r1 = r0 + 8;
            if (n_g < N)
                Vout[(size_t)r1 * N + n_g] = fmaxf(acc[im][in8][2] + bv0, 0.f);
            if (n_g + 1 < N)
                Vout[(size_t)r1 * N + n_g + 1] = fmaxf(acc[im][in8][3] + bv1, 0.f);
        }
    }
}

// ---------------- persistent LSTM with hardware cluster barrier ----------------
// grid (8 nt, 8 mt, 2 dir), cluster (8,1,1): each cluster = the 8 n-blocks of one (mt,dir)
__global__ void __launch_bounds__(512) lstm_persistent(const int* __restrict__ sem) {
    extern __shared__ __align__(16) unsigned char smraw[];
    uint32_t sbase = (uint32_t)__cvta_generic_to_shared(smraw);
    const int dir = blockIdx.z, mt = blockIdx.y, nt = blockIdx.x;
    const int m0 = mt * 128, n0 = nt * 160;

    int tid = threadIdx.x, lane = tid & 31, wid = tid >> 5;
    int g = lane >> 2, t4 = lane & 3;
    int wm = (wid >> 2) * 32, wn = (wid & 3) * 40;
    int parity = lane & 1;

    uint32_t Abase = sbase;
    uint32_t Bbase = sbase + 32768;

    {
        const __nv_bfloat16* Whi = g_Whi[dir];
        const __nv_bfloat16* Wlo = g_Wlo[dir];
        for (int p = tid; p < 19 * 640; p += 512) {
            int kc = p / 640, r = p - kc * 640;
            int row = r >> 2, seg = r & 3;
            int plane = seg >> 1, half = seg & 1;
            const __nv_bfloat16* src = plane ? Wlo : Whi;
            uint4 v = *(const uint4*)(src + (size_t)(n0 + row) * KP + kc * 16 + half * 8);
            *(uint4*)(smraw + 32768 + kc * 10240 + swz(row, seg)) = v;
        }
    }
    __syncthreads();

    const float* sproj = g_sproj[dir];
    const float* wproj = g_wproj[dir];

    float cst[2][5];
#pragma unroll
    for (int a = 0; a < 2; a++)
#pragma unroll
        for (int b = 0; b < 5; b++) cst[a][b] = 0.f;

    for (int s = 0; s < L; s++) {
        int t = dir ? (L - 1 - s) : s;

        float acc[2][5][4];
#pragma unroll
        for (int a = 0; a < 2; a++)
#pragma unroll
            for (int b = 0; b < 5; b++)
#pragma unroll
                for (int c = 0; c < 4; c++) acc[a][b][c] = 0.f;

        if (s > 0) {
            const uint32_t* Apk = g_hpk[dir][(s - 1) & 1];
            uint4 ua[2];
            int arow = tid >> 2, akq = tid & 3;
            auto loadA = [&](int kc, int sl) {
                ua[sl] = ldcg4(Apk + (size_t)(m0 + arow) * KP + kc * 16 + akq * 4);
            };
            auto storeA = [&](int sl, int buf) {
                uint4 u = ua[sl];
                uint32_t hiA = __byte_perm(u.x, u.y, 0x5410);
                uint32_t hiB = __byte_perm(u.z, u.w, 0x5410);
                uint32_t loA = __byte_perm(u.x, u.y, 0x7632);
                uint32_t loB = __byte_perm(u.z, u.w, 0x7632);
                uint32_t base = (uint32_t)(buf * 8192);
                *(uint2*)(smraw + base + swz(arow, akq >> 1) + (akq & 1) * 8)
                    = make_uint2(hiA, hiB);
                *(uint2*)(smraw + base + swz(arow, (akq >> 1) + 2) + (akq & 1) * 8)
                    = make_uint2(loA, loB);
            };
            const int NC = 19, NG = 10;
            loadA(0, 0); loadA(1, 1);
            storeA(0, 0); storeA(1, 1);
            __syncthreads();
            for (int gg = 0; gg < NG; gg++) {
                int base2 = 2 * gg;
                if (gg + 1 < NG) {
                    loadA(base2 + 2, 0);
                    if (base2 + 3 < NC) loadA(base2 + 3, 1);
                }
                mma_chunk64(Abase + (uint32_t)((base2 & 3) * 8192),
                            Bbase + (uint32_t)(base2 * 10240), lane, wm, wn, acc);
                if (base2 + 1 < NC)
                    mma_chunk64(Abase + (uint32_t)(((base2 + 1) & 3) * 8192),
                                Bbase + (uint32_t)((base2 + 1) * 10240), lane, wm, wn, acc);
                if (gg + 1 < NG) {
                    storeA(0, (base2 + 2) & 3);
                    if (base2 + 3 < NC) storeA(1, (base2 + 3) & 3);
                }
                __syncthreads();
            }
        }

        uint32_t* Hpk = g_hpk[dir][s & 1];
#pragma unroll
        for (int im = 0; im < 2; im++) {
            int rowl = wm + im * 16 + g + (parity ? 8 : 0);
            int b = m0 + rowl;
            int idx = sem[b * L + t];
            const float* sp = sproj + (size_t)idx * G4;
            const float* wp = wproj + (size_t)b * G4;
            float wmul = (idx != 0) ? 1.f : 0.f;
#pragma unroll
            for (int n8 = 0; n8 < 5; n8++) {
                float c0 = acc[im][n8][0], c1 = acc[im][n8][1];
                float c2 = acc[im][n8][2], c3 = acc[im][n8][3];
                float s1 = parity ? c0 : c2;
                float s2 = parity ? c1 : c3;
                float r1 = __shfl_xor_sync(0xffffffffu, s1, 1);
                float r2 = __shfl_xor_sync(0xffffffffu, s2, 1);
                float gi, gf, gg2, go;
                if (!parity) { gi = c0; gf = c1; gg2 = r1; go = r2; }
                else         { gi = r1; gf = r2; gg2 = c2; go = c3; }
                int j = (n0 + wn + n8 * 8 + 2 * t4) >> 2;
                if (j < H) {
                    float4 spv = *(const float4*)(sp + 4 * j);
                    float4 wpv = *(const float4*)(wp + 4 * j);
                    gi  += spv.x + wmul * wpv.x;
                    gf  += spv.y + wmul * wpv.y;
                    gg2 += spv.z + wmul * wpv.z;
                    go  += spv.w + wmul * wpv.w;
                    float ig = sigf(gi);
                    float fg = sigf(gf);
                    float gt = tanhfast(gg2);
                    float og = sigf(go);
                    float cn = fg * cst[im][n8] + ig * gt;
                    cst[im][n8] = cn;
                    float h = og * tanhfast(cn);
                    float hh, hl; spb(h, hh, hl);
                    uint32_t pk = pack2(hh, hl);
                    Hpk[(size_t)b * KP + j] = pk;
                    g_Vpk[(size_t)(b * L + t) * VROW + dir * H + j] = pk;
                }
            }
        }

        // hardware cluster barrier (release on arrive, acquire on wait)
        if (s < L - 1) {
            asm volatile("barrier.cluster.arrive.aligned;" ::: "memory");
            asm volatile("barrier.cluster.wait.aligned;" ::: "memory");
        }
    }
}

// ---------------- launch ----------------
extern "C" void kernel_launch(void* const* d_in, const int* in_sizes, int n_in,
                              void* d_out, int out_size) {
    const int*   word  = (const int*)d_in[0];
    const int*   sem   = (const int*)d_in[1];
    const float* wt    = (const float*)d_in[2];
    const float* st    = (const float*)d_in[3];
    const float* Wih_f = (const float*)d_in[4];
    const float* Whh_f = (const float*)d_in[5];
    const float* bih_f = (const float*)d_in[6];
    const float* bhh_f = (const float*)d_in[7];
    const float* Wih_b = (const float*)d_in[8];
    const float* Whh_b = (const float*)d_in[9];
    const float* bih_b = (const float*)d_in[10];
    const float* bhh_b = (const float*)d_in[11];
    const float* Wa    = (const float*)d_in[12];
    const float* ba    = (const float*)d_in[13];
    const float* Wb    = (const float*)d_in[14];
    const float* bb    = (const float*)d_in[15];

    float* out    = (float*)d_out;
    float* Vout   = out;
    float* vg_out = out + (size_t)B * L * H;

    void* p;
    float *psf, *psb, *pwf, *pwb;
    cudaGetSymbolAddress(&p, g_sproj); psf = (float*)p; psb = psf + (size_t)VS * G4;
    cudaGetSymbolAddress(&p, g_wproj); pwf = (float*)p; pwb = pwf + (size_t)B * G4;

    cudaFuncSetAttribute(lstm_persistent,
                         cudaFuncAttributeMaxDynamicSharedMemorySize, PSMEM);
    cudaFuncSetAttribute(lstm_persistent,
                         cudaFuncAttributeNonPortableClusterSizeAllowed, 1);
    cudaFuncSetAttribute(gemm_ff,
                         cudaFuncAttributeMaxDynamicSharedMemorySize, FFSMEM);
    cudaFuncSetAttribute(gemm_v,
                         cudaFuncAttributeMaxDynamicSharedMemorySize, FFSMEM);

    init_kernel<<<(2 * 2 * B * KP + 255) / 256, 256>>>();
    prep_whh<<<(2 * NPAD * KP + 255) / 256, 256>>>(Whh_f, Whh_b);
    embed_kernel<<<B, 320>>>(word, sem, wt, st);

    gemm_ff<<<432, 512, FFSMEM>>>(Wb, bb, st, Wih_f, Wih_b,
                                  bih_f, bhh_f, bih_b, bhh_b,
                                  vg_out, psf, psb, pwf, pwb);

    // persistent lstm with cluster (8,1,1) along nt
    {
        cudaLaunchConfig_t cfg = {};
        cfg.gridDim = dim3(8, 8, 2);
        cfg.blockDim = dim3(512, 1, 1);
        cfg.dynamicSmemBytes = PSMEM;
        cudaLaunchAttribute attrs[1];
        attrs[0].id = cudaLaunchAttributeClusterDimension;
        attrs[0].val.clusterDim.x = 8;
        attrs[0].val.clusterDim.y = 1;
        attrs[0].val.clusterDim.z = 1;
        cfg.attrs = attrs;
        cfg.numAttrs = 1;
        cudaLaunchKernelEx(&cfg, lstm_persistent, sem);
    }

    gemm_v<<<dim3(2, 144), 512, FFSMEM>>>(Wa, ba, Vout);
}

// round 14
// speedup vs baseline: 1.6671x; 1.6671x over previous
#include <cuda_runtime.h>
#include <cuda_bf16.h>
#include <math.h>
#include <stdint.h>

#define B 1024
#define L 18
#define E 300
#define H 300
#define G4 1200
#define KP 304          // H padded to 16
#define NPAD 1280       // G4 padded to 160-tile
#define VS 2186
#define BL (B*L)

#define ABYTES 10240    // 128 rows * 80 B
#define BUFB   23040    // A(10240) + B(160*80=12800)
#define FFSMEM (4*BUFB)
#define PSMEM (4*8192 + 19*10240)   // 227328

// ---------------- scratch ----------------
__device__ float g_ag[B * E];
__device__ float g_w [B * E];
__device__ float g_sproj[2][VS * G4];     // interleaved cols n'=4j+gate
__device__ float g_wproj[2][B * G4];      // interleaved
__device__ float g_Vh[BL * 2 * H];        // concat(hf, hb), f32
__device__ uint32_t g_hpk[2][2][B * KP];  // h packed (hi,lo) bf16x2 [dir][buf]
__device__ __nv_bfloat16 g_Whi[2][NPAD * KP];  // Whh permuted [n'][k] hi
__device__ __nv_bfloat16 g_Wlo[2][NPAD * KP];  // lo
__device__ int g_cnt[2][8];                    // group barriers [dir][m-tile]

// ---------------- helpers ----------------
__device__ __forceinline__ void spb(float v, float& hi, float& lo) {
    hi = __bfloat162float(__float2bfloat16(v));
    lo = v - hi;
}
__device__ __forceinline__ uint32_t pack2(float x, float y) {
    __nv_bfloat162 v = __floats2bfloat162_rn(x, y);
    return *reinterpret_cast<uint32_t*>(&v);
}
__device__ __forceinline__ void ldsm4(uint32_t* r, uint32_t addr) {
    asm volatile("ldmatrix.sync.aligned.m8n8.x4.shared.b16 {%0,%1,%2,%3}, [%4];"
        : "=r"(r[0]), "=r"(r[1]), "=r"(r[2]), "=r"(r[3]) : "r"(addr));
}
__device__ __forceinline__ void ldsm2(uint32_t& r0, uint32_t& r1, uint32_t addr) {
    asm volatile("ldmatrix.sync.aligned.m8n8.x2.shared.b16 {%0,%1}, [%2];"
        : "=r"(r0), "=r"(r1) : "r"(addr));
}
__device__ __forceinline__ void mma16(float* c, const uint32_t* a, const uint32_t* b) {
    asm volatile("mma.sync.aligned.m16n8k16.row.col.f32.bf16.bf16.f32 "
        "{%0,%1,%2,%3},{%4,%5,%6,%7},{%8,%9},{%0,%1,%2,%3};"
        : "+f"(c[0]), "+f"(c[1]), "+f"(c[2]), "+f"(c[3])
        : "r"(a[0]), "r"(a[1]), "r"(a[2]), "r"(a[3]), "r"(b[0]), "r"(b[1]));
}
__device__ __forceinline__ uint4 ldcg4(const void* p) {
    uint4 v;
    asm volatile("ld.global.cg.v4.u32 {%0,%1,%2,%3}, [%4];"
        : "=r"(v.x), "=r"(v.y), "=r"(v.z), "=r"(v.w) : "l"(p));
    return v;
}
__device__ __forceinline__ uint32_t swz(int row, int seg) {
    return (uint32_t)(row * 64 + (((seg + (row >> 1)) & 3) << 4));
}
__device__ __forceinline__ float sigf(float x) {
    return __fdividef(1.f, 1.f + __expf(-x));
}
__device__ __forceinline__ float tanhfast(float x) {
    float xc = fminf(fmaxf(x, -15.f), 15.f);
    float e = __expf(2.f * xc);
    return __fdividef(e - 1.f, e + 1.f);
}

// ---------------- mma chunk, warp tile 32x40, 80B-stride layout ----------------
__device__ __forceinline__ void mma_chunk80(uint32_t Ab, uint32_t Bb, int lane,
                                            int wm, int wn, float (&acc)[2][5][4]) {
    int r8 = lane & 7, sel = lane >> 3;
    int arow = ((sel & 1) << 3) + r8;
    int akoff = (sel >> 1) << 4;
    uint32_t ah[2][4], al[2][4];
#pragma unroll
    for (int im = 0; im < 2; im++) {
        uint32_t addr = Ab + (uint32_t)((wm + im * 16 + arow) * 80 + akoff);
        ldsm4(ah[im], addr);
        ldsm4(al[im], addr + 32);
    }
    uint32_t bh[5][2], bl[5][2];
    int brow = ((sel >> 1) << 3) + r8;
    int bkoff = (sel & 1) << 4;
#pragma unroll
    for (int j2 = 0; j2 < 2; j2++) {
        uint32_t addr = Bb + (uint32_t)((wn + j2 * 16 + brow) * 80 + bkoff);
        uint32_t t[4];
        ldsm4(t, addr);
        bh[2 * j2][0] = t[0]; bh[2 * j2][1] = t[1];
        bh[2 * j2 + 1][0] = t[2]; bh[2 * j2 + 1][1] = t[3];
        ldsm4(t, addr + 32);
        bl[2 * j2][0] = t[0]; bl[2 * j2][1] = t[1];
        bl[2 * j2 + 1][0] = t[2]; bl[2 * j2 + 1][1] = t[3];
    }
    {
        int row2 = lane & 7;
        int koff2 = ((lane >> 3) & 1) << 4;
        uint32_t addr = Bb + (uint32_t)((wn + 32 + row2) * 80 + koff2);
        ldsm2(bh[4][0], bh[4][1], addr);
        ldsm2(bl[4][0], bl[4][1], addr + 32);
    }
#pragma unroll
    for (int n8 = 0; n8 < 5; n8++)
#pragma unroll
        for (int im = 0; im < 2; im++) {
            mma16(acc[im][n8], ah[im], bh[n8]);
            mma16(acc[im][n8], al[im], bh[n8]);
            mma16(acc[im][n8], ah[im], bl[n8]);
        }
}

// ---------------- mma chunk, warp tile 32x40, swizzled 64B layout ----------------
__device__ __forceinline__ void mma_chunk64(uint32_t Ab, uint32_t Bb, int lane,
                                            int wm, int wn, float (&acc)[2][5][4]) {
    int r8 = lane & 7, sel = lane >> 3;
    int arow = ((sel & 1) << 3) + r8;
    int akseg = sel >> 1;
    uint32_t ah[2][4], al[2][4];
#pragma unroll
    for (int im = 0; im < 2; im++) {
        int row = wm + im * 16 + arow;
        ldsm4(ah[im], Ab + swz(row, akseg));
        ldsm4(al[im], Ab + swz(row, akseg + 2));
    }
    uint32_t bh[5][2], bl[5][2];
    int brow = ((sel >> 1) << 3) + r8;
    int bkseg = sel & 1;
#pragma unroll
    for (int j2 = 0; j2 < 2; j2++) {
        int row = wn + j2 * 16 + brow;
        uint32_t t[4];
        ldsm4(t, Bb + swz(row, bkseg));
        bh[2 * j2][0] = t[0]; bh[2 * j2][1] = t[1];
        bh[2 * j2 + 1][0] = t[2]; bh[2 * j2 + 1][1] = t[3];
        ldsm4(t, Bb + swz(row, bkseg + 2));
        bl[2 * j2][0] = t[0]; bl[2 * j2][1] = t[1];
        bl[2 * j2 + 1][0] = t[2]; bl[2 * j2 + 1][1] = t[3];
    }
    {
        int row = wn + 32 + (lane & 7);
        int seg = (lane >> 3) & 1;
        ldsm2(bh[4][0], bh[4][1], Bb + swz(row, seg));
        ldsm2(bl[4][0], bl[4][1], Bb + swz(row, seg + 2));
    }
#pragma unroll
    for (int n8 = 0; n8 < 5; n8++)
#pragma unroll
        for (int im = 0; im < 2; im++) {
            mma16(acc[im][n8], ah[im], bh[n8]);
            mma16(acc[im][n8], al[im], bh[n8]);
            mma16(acc[im][n8], ah[im], bl[n8]);
        }
}

// ---------------- merged prologue: zero state + counters + Whh prep ----------------
__global__ void prologue_kernel(const float* __restrict__ Wf,
                                const float* __restrict__ Wb) {
    int i = blockIdx.x * blockDim.x + threadIdx.x;
    // part 1: zero h planes + barrier counters
    if (i < 2 * 2 * B * KP) (&g_hpk[0][0][0])[i] = 0u;
    if (i < 16) (&g_cnt[0][0])[i] = 0;
    // part 2: Whh -> permuted interleaved planes
    if (i < 2 * NPAD * KP) {
        int dir = i / (NPAD * KP);
        int r = i - dir * (NPAD * KP);
        int np = r / KP, k = r - np * KP;
        float v = 0.f;
        if (np < G4 && k < H) {
            const float* W = dir ? Wb : Wf;
            v = W[(size_t)((np & 3) * H + (np >> 2)) * H + k];
        }
        float hi, lo; spb(v, hi, lo);
        g_Whi[dir][r] = __float2bfloat16(hi);
        g_Wlo[dir][r] = __float2bfloat16(lo);
    }
}

__global__ void embed_kernel(const int* __restrict__ word,
                             const int* __restrict__ sem,
                             const float* __restrict__ wt,
                             const float* __restrict__ st) {
    int b = blockIdx.x;
    int e = threadIdx.x;
    __shared__ int sidx[L];
    __shared__ int widx;
    if (e < L) sidx[e] = sem[b * L + e];
    if (e == 0) widx = word[b];
    __syncthreads();
    if (e < E) {
        float acc = 0.f;
#pragma unroll
        for (int l = 0; l < L; l++) acc += st[sidx[l] * E + e];
        g_ag[b * E + e] = acc * (1.f / (float)L);
        g_w [b * E + e] = wt[widx * E + e];
    }
}

// ---------------- feed-forward gemm body (4-deep ring, sync per 2 chunks) ----------------
__device__ __forceinline__ void gemm_body(
    unsigned char* smraw,
    const float* A, int lda, const float* W, int ldw, int imap,
    const float* b1, const float* b2, float* C,
    int M, int N, int K, int dorelu, int bx, int by)
{
    uint32_t sbase = (uint32_t)__cvta_generic_to_shared(smraw);
    uint32_t* smw = (uint32_t*)smraw;

    int tid = threadIdx.x, lane = tid & 31, wid = tid >> 5;
    int g = lane >> 2, t4 = lane & 3;
    int wm = (wid >> 2) * 32, wn = (wid & 3) * 40;
    int m0 = by * 128, n0 = bx * 160;

    float acc[2][5][4];
#pragma unroll
    for (int a = 0; a < 2; a++)
#pragma unroll
        for (int b = 0; b < 5; b++)
#pragma unroll
            for (int c = 0; c < 4; c++) acc[a][b][c] = 0.f;

    int NC = (K + 15) / 16;
    int NG = (NC + 1) / 2;
    float4 ra[2], rb[2][2];

    auto loadregs = [&](int kc, int sl) {
        int k0 = kc * 16;
        {
            int row = tid >> 2, q4 = tid & 3;
            int gm = m0 + row, kk = k0 + q4 * 4;
            float4 v = make_float4(0.f, 0.f, 0.f, 0.f);
            if (gm < M) {
                const float* ap = A + (size_t)gm * lda;
                if (kk + 3 < K) v = *(const float4*)(ap + kk);
                else {
                    if (kk + 0 < K) v.x = ap[kk + 0];
                    if (kk + 1 < K) v.y = ap[kk + 1];
                    if (kk + 2 < K) v.z = ap[kk + 2];
                    if (kk + 3 < K) v.w = ap[kk + 3];
                }
            }
            ra[sl] = v;
        }
#pragma unroll
        for (int q = 0; q < 2; q++) {
            int p = tid + q * 512;
            float4 v = make_float4(0.f, 0.f, 0.f, 0.f);
            if (p < 640) {
                int row = p >> 2, q4 = p & 3;
                int nr = n0 + row, kk = k0 + q4 * 4;
                if (nr < N) {
                    int grow = imap ? ((nr & 3) * H + (nr >> 2)) : nr;
                    const float* wp = W + (size_t)grow * ldw;
                    if (kk + 3 < K) v = *(const float4*)(wp + kk);
                    else {
                        if (kk + 0 < K) v.x = wp[kk + 0];
                        if (kk + 1 < K) v.y = wp[kk + 1];
                        if (kk + 2 < K) v.z = wp[kk + 2];
                        if (kk + 3 < K) v.w = wp[kk + 3];
                    }
                }
            }
            rb[sl][q] = v;
        }
    };
    auto storeregs = [&](int sl, int buf) {
        uint32_t* Aw = smw + buf * (BUFB / 4);
        uint32_t* Bw = Aw + ABYTES / 4;
        {
            int row = tid >> 2, q4 = tid & 3;
            float h0, l0, h1, l1, h2, l2, h3, l3;
            spb(ra[sl].x, h0, l0); spb(ra[sl].y, h1, l1);
            spb(ra[sl].z, h2, l2); spb(ra[sl].w, h3, l3);
            Aw[row * 20 + q4 * 2]     = pack2(h0, h1);
            Aw[row * 20 + q4 * 2 + 1] = pack2(h2, h3);
            Aw[row * 20 + 8 + q4 * 2]     = pack2(l0, l1);
            Aw[row * 20 + 8 + q4 * 2 + 1] = pack2(l2, l3);
        }
#pragma unroll
        for (int q = 0; q < 2; q++) {
            int p = tid + q * 512;
            if (p < 640) {
                int row = p >> 2, q4 = p & 3;
                float h0, l0, h1, l1, h2, l2, h3, l3;
                spb(rb[sl][q].x, h0, l0); spb(rb[sl][q].y, h1, l1);
                spb(rb[sl][q].z, h2, l2); spb(rb[sl][q].w, h3, l3);
                Bw[row * 20 + q4 * 2]     = pack2(h0, h1);
                Bw[row * 20 + q4 * 2 + 1] = pack2(h2, h3);
                Bw[row * 20 + 8 + q4 * 2]     = pack2(l0, l1);
                Bw[row * 20 + 8 + q4 * 2 + 1] = pack2(l2, l3);
            }
        }
    };

    loadregs(0, 0);
    if (1 < NC) loadregs(1, 1);
    storeregs(0, 0);
    if (1 < NC) storeregs(1, 1);
    __syncthreads();
    for (int gg = 0; gg < NG; gg++) {
        int base2 = 2 * gg;
        if (gg + 1 < NG) {
            loadregs(base2 + 2, 0);
            if (base2 + 3 < NC) loadregs(base2 + 3, 1);
        }
        mma_chunk80(sbase + (uint32_t)((base2 & 3) * BUFB),
                    sbase + (uint32_t)((base2 & 3) * BUFB) + ABYTES, lane, wm, wn, acc);
        if (base2 + 1 < NC)
            mma_chunk80(sbase + (uint32_t)(((base2 + 1) & 3) * BUFB),
                        sbase + (uint32_t)(((base2 + 1) & 3) * BUFB) + ABYTES, lane, wm, wn, acc);
        if (gg + 1 < NG) {
            storeregs(0, (base2 + 2) & 3);
            if (base2 + 3 < NC) storeregs(1, (base2 + 3) & 3);
        }
        __syncthreads();
    }

#pragma unroll
    for (int in8 = 0; in8 < 5; in8++) {
        int n_g = n0 + wn + in8 * 8 + 2 * t4;
        float bv0 = 0.f, bv1 = 0.f;
        if (n_g < N) {
            int i0 = imap ? ((n_g & 3) * H + (n_g >> 2)) : n_g;
            if (b1) bv0 += b1[i0];
            if (b2) bv0 += b2[i0];
        }
        if (n_g + 1 < N) {
            int i1 = imap ? (((n_g + 1) & 3) * H + ((n_g + 1) >> 2)) : (n_g + 1);
            if (b1) bv1 += b1[i1];
            if (b2) bv1 += b2[i1];
        }
#pragma unroll
        for (int im = 0; im < 2; im++) {
            int r0 = m0 + wm + im * 16 + g;
            if (r0 < M) {
                if (n_g < N) {
                    float v = acc[im][in8][0] + bv0;
                    if (dorelu) v = fmaxf(v, 0.f);
                    C[(size_t)r0 * N + n_g] = v;
                }
                if (n_g + 1 < N) {
                    float v = acc[im][in8][1] + bv1;
                    if (dorelu) v = fmaxf(v, 0.f);
                    C[(size_t)r0 * N + n_g + 1] = v;
                }
            }
            int r1 = r0 + 8;
            if (r1 < M) {
                if (n_g < N) {
                    float v = acc[im][in8][2] + bv0;
                    if (dorelu) v = fmaxf(v, 0.f);
                    C[(size_t)r1 * N + n_g] = v;
                }
                if (n_g + 1 < N) {
                    float v = acc[im][in8][3] + bv1;
                    if (dorelu) v = fmaxf(v, 0.f);
                    C[(size_t)r1 * N + n_g + 1] = v;
                }
            }
        }
    }
}

// ---------------- merged feed-forward launch ----------------
__global__ void __launch_bounds__(512) gemm_ff(
    const float* Wb_, const float* bb_, const float* st,
    const float* Wih_f, const float* Wih_b,
    const float* bih_f, const float* bhh_f,
    const float* bih_b, const float* bhh_b,
    float* vg_out, float* psf, float* psb, float* pwf, float* pwb)
{
    extern __shared__ __align__(16) unsigned char smdyn[];
    int bid = blockIdx.x;
    if (bid < 16) {
        gemm_body(smdyn, g_ag, E, Wb_, E, 0, bb_, nullptr, vg_out,
                  B, E, E, 1, bid & 1, bid >> 1);
    } else if (bid < 160) {
        int r = bid - 16;
        gemm_body(smdyn, st, E, Wih_f + E, 2 * E, 1, bih_f, bhh_f, psf,
                  VS, G4, E, 0, r & 7, r >> 3);
    } else if (bid < 304) {
        int r = bid - 160;
        gemm_body(smdyn, st, E, Wih_b + E, 2 * E, 1, bih_b, bhh_b, psb,
                  VS, G4, E, 0, r & 7, r >> 3);
    } else if (bid < 368) {
        int r = bid - 304;
        gemm_body(smdyn, g_w, E, Wih_f, 2 * E, 1, nullptr, nullptr, pwf,
                  B, G4, E, 0, r & 7, r >> 3);
    } else {
        int r = bid - 368;
        gemm_body(smdyn, g_w, E, Wih_b, 2 * E, 1, nullptr, nullptr, pwb,
                  B, G4, E, 0, r & 7, r >> 3);
    }
}

__global__ void __launch_bounds__(512) gemm_v(
    const float* Wa, const float* ba, float* Vout)
{
    extern __shared__ __align__(16) unsigned char smdyn[];
    gemm_body(smdyn, g_Vh, 2 * H, Wa, 2 * H, 0, ba, nullptr, Vout,
              BL, H, 2 * H, 1, blockIdx.x, blockIdx.y);
}

// ---------------- persistent LSTM (round-8 champion config) ----------------
__global__ void __launch_bounds__(512) lstm_persistent(const int* __restrict__ sem) {
    extern __shared__ __align__(16) unsigned char smraw[];
    uint32_t sbase = (uint32_t)__cvta_generic_to_shared(smraw);
    const int dir = blockIdx.z, mt = blockIdx.y, nt = blockIdx.x;
    const int m0 = mt * 128, n0 = nt * 160;

    int tid = threadIdx.x, lane = tid & 31, wid = tid >> 5;
    int g = lane >> 2, t4 = lane & 3;
    int wm = (wid >> 2) * 32, wn = (wid & 3) * 40;
    int parity = lane & 1;

    uint32_t Abase = sbase;           // 4 buffers x 8192
    uint32_t Bbase = sbase + 32768;   // 19 chunks x 10240

    {
        const __nv_bfloat16* Whi = g_Whi[dir];
        const __nv_bfloat16* Wlo = g_Wlo[dir];
        for (int p = tid; p < 19 * 640; p += 512) {
            int kc = p / 640, r = p - kc * 640;
            int row = r >> 2, seg = r & 3;
            int plane = seg >> 1, half = seg & 1;
            const __nv_bfloat16* src = plane ? Wlo : Whi;
            uint4 v = *(const uint4*)(src + (size_t)(n0 + row) * KP + kc * 16 + half * 8);
            *(uint4*)(smraw + 32768 + kc * 10240 + swz(row, seg)) = v;
        }
    }
    __syncthreads();

    const float* sproj = g_sproj[dir];
    const float* wproj = g_wproj[dir];

    float cst[2][5];
#pragma unroll
    for (int a = 0; a < 2; a++)
#pragma unroll
        for (int b = 0; b < 5; b++) cst[a][b] = 0.f;

    for (int s = 0; s < L; s++) {
        float acc[2][5][4];
#pragma unroll
        for (int a = 0; a < 2; a++)
#pragma unroll
            for (int b = 0; b < 5; b++)
#pragma unroll
                for (int c = 0; c < 4; c++) acc[a][b][c] = 0.f;

        if (s > 0) {
            const uint32_t* Apk = g_hpk[dir][(s - 1) & 1];
            uint4 ua[2];
            int arow = tid >> 2, akq = tid & 3;
            auto loadA = [&](int kc, int sl) {
                ua[sl] = ldcg4(Apk + (size_t)(m0 + arow) * KP + kc * 16 + akq * 4);
            };
            auto storeA = [&](int sl, int buf) {
                uint4 u = ua[sl];
                uint32_t hiA = __byte_perm(u.x, u.y, 0x5410);
                uint32_t hiB = __byte_perm(u.z, u.w, 0x5410);
                uint32_t loA = __byte_perm(u.x, u.y, 0x7632);
                uint32_t loB = __byte_perm(u.z, u.w, 0x7632);
                uint32_t base = (uint32_t)(buf * 8192);
                *(uint2*)(smraw + base + swz(arow, akq >> 1) + (akq & 1) * 8)
                    = make_uint2(hiA, hiB);
                *(uint2*)(smraw + base + swz(arow, (akq >> 1) + 2) + (akq & 1) * 8)
                    = make_uint2(loA, loB);
            };
            const int NC = 19, NG = 10;
            loadA(0, 0); loadA(1, 1);
            storeA(0, 0); storeA(1, 1);
            __syncthreads();
            for (int gg = 0; gg < NG; gg++) {
                int base2 = 2 * gg;
                if (gg + 1 < NG) {
                    loadA(base2 + 2, 0);
                    if (base2 + 3 < NC) loadA(base2 + 3, 1);
                }
                mma_chunk64(Abase + (uint32_t)((base2 & 3) * 8192),
                            Bbase + (uint32_t)(base2 * 10240), lane, wm, wn, acc);
                if (base2 + 1 < NC)
                    mma_chunk64(Abase + (uint32_t)(((base2 + 1) & 3) * 8192),
                                Bbase + (uint32_t)((base2 + 1) * 10240), lane, wm, wn, acc);
                if (gg + 1 < NG) {
                    storeA(0, (base2 + 2) & 3);
                    if (base2 + 3 < NC) storeA(1, (base2 + 3) & 3);
                }
                __syncthreads();
            }
        }

        // epilogue
        int t = dir ? (L - 1 - s) : s;
        uint32_t* Hpk = g_hpk[dir][s & 1];
#pragma unroll
        for (int im = 0; im < 2; im++) {
            int rowl = wm + im * 16 + g + (parity ? 8 : 0);
            int b = m0 + rowl;
            int idx = sem[b * L + t];
            const float* sp = sproj + (size_t)idx * G4;
            const float* wp = wproj + (size_t)b * G4;
            float wmul = (idx != 0) ? 1.f : 0.f;
#pragma unroll
            for (int n8 = 0; n8 < 5; n8++) {
                float c0 = acc[im][n8][0], c1 = acc[im][n8][1];
                float c2 = acc[im][n8][2], c3 = acc[im][n8][3];
                float s1 = parity ? c0 : c2;
                float s2 = parity ? c1 : c3;
                float r1 = __shfl_xor_sync(0xffffffffu, s1, 1);
                float r2 = __shfl_xor_sync(0xffffffffu, s2, 1);
                float gi, gf, gg2, go;
                if (!parity) { gi = c0; gf = c1; gg2 = r1; go = r2; }
                else         { gi = r1; gf = r2; gg2 = c2; go = c3; }
                int j = (n0 + wn + n8 * 8 + 2 * t4) >> 2;
                if (j < H) {
                    float4 spv = *(const float4*)(sp + 4 * j);
                    float4 wpv = *(const float4*)(wp + 4 * j);
                    gi  += spv.x + wmul * wpv.x;
                    gf  += spv.y + wmul * wpv.y;
                    gg2 += spv.z + wmul * wpv.z;
                    go  += spv.w + wmul * wpv.w;
                    float ig = sigf(gi);
                    float fg = sigf(gf);
                    float gt = tanhfast(gg2);
                    float og = sigf(go);
                    float cn = fg * cst[im][n8] + ig * gt;
                    cst[im][n8] = cn;
                    float h = og * tanhfast(cn);
                    g_Vh[(size_t)(b * L + t) * (2 * H) + dir * H + j] = h;
                    float hh, hl; spb(h, hh, hl);
                    Hpk[(size_t)b * KP + j] = pack2(hh, hl);
                }
            }
        }

        // group barrier: release/acquire
        if (s < L - 1) {
            __syncthreads();
            if (tid == 0) {
                int* cp = &g_cnt[dir][mt];
                asm volatile("red.release.gpu.global.add.s32 [%0], 1;"
                             :: "l"(cp) : "memory");
                int target = 8 * (s + 1);
                int v;
                while (true) {
                    asm volatile("ld.acquire.gpu.global.b32 %0, [%1];"
                                 : "=r"(v) : "l"(cp) : "memory");
                    if (v >= target) break;
                    __nanosleep(64);
                }
            }
            __syncthreads();
        }
    }
}

// ---------------- launch ----------------
extern "C" void kernel_launch(void* const* d_in, const int* in_sizes, int n_in,
                              void* d_out, int out_size) {
    const int*   word  = (const int*)d_in[0];
    const int*   sem   = (const int*)d_in[1];
    const float* wt    = (const float*)d_in[2];
    const float* st    = (const float*)d_in[3];
    const float* Wih_f = (const float*)d_in[4];
    const float* Whh_f = (const float*)d_in[5];
    const float* bih_f = (const float*)d_in[6];
    const float* bhh_f = (const float*)d_in[7];
    const float* Wih_b = (const float*)d_in[8];
    const float* Whh_b = (const float*)d_in[9];
    const float* bih_b = (const float*)d_in[10];
    const float* bhh_b = (const float*)d_in[11];
    const float* Wa    = (const float*)d_in[12];
    const float* ba    = (const float*)d_in[13];
    const float* Wb    = (const float*)d_in[14];
    const float* bb    = (const float*)d_in[15];

    float* out    = (float*)d_out;
    float* Vout   = out;
    float* vg_out = out + (size_t)B * L * H;

    void* p;
    float *psf, *psb, *pwf, *pwb;
    cudaGetSymbolAddress(&p, g_sproj); psf = (float*)p; psb = psf + (size_t)VS * G4;
    cudaGetSymbolAddress(&p, g_wproj); pwf = (float*)p; pwb = pwf + (size_t)B * G4;

    cudaFuncSetAttribute(lstm_persistent,
                         cudaFuncAttributeMaxDynamicSharedMemorySize, PSMEM);
    cudaFuncSetAttribute(gemm_ff,
                         cudaFuncAttributeMaxDynamicSharedMemorySize, FFSMEM);
    cudaFuncSetAttribute(gemm_v,
                         cudaFuncAttributeMaxDynamicSharedMemorySize, FFSMEM);

    prologue_kernel<<<(2 * NPAD * KP + 255) / 256, 256>>>(Whh_f, Whh_b);
    embed_kernel<<<B, 320>>>(word, sem, wt, st);

    gemm_ff<<<432, 512, FFSMEM>>>(Wb, bb, st, Wih_f, Wih_b,
                                  bih_f, bhh_f, bih_b, bhh_b,
                                  vg_out, psf, psb, pwf, pwb);

    lstm_persistent<<<dim3(8, 8, 2), 512, PSMEM>>>(sem);

    gemm_v<<<dim3(2, 144), 512, FFSMEM>>>(Wa, ba, Vout);
}

// round 15
// speedup vs baseline: 1.8239x; 1.0940x over previous
#include <cuda_runtime.h>
#include <cuda_bf16.h>
#include <math.h>
#include <stdint.h>

#define B 1024
#define L 18
#define E 300
#define H 300
#define G4 1200
#define KP 304          // H padded to 16
#define NPAD 1280       // G4 padded to 160-tile
#define VS 2186
#define BL (B*L)

#define ABYTES 10240    // 128 rows * 80 B
#define BUFB   23040    // A(10240) + B(160*80=12800)
#define FFSMEM (4*BUFB)
#define PSMEM (19*10240)   // 194560: B tile only; A comes direct from L2

// ---------------- scratch ----------------
__device__ float g_ag[B * E];
__device__ float g_w [B * E];
__device__ float g_sproj[2][VS * G4];     // interleaved cols n'=4j+gate
__device__ float g_wproj[2][B * G4];      // interleaved
__device__ float g_Vh[BL * 2 * H];        // concat(hf, hb), f32
__device__ uint32_t g_hpk[2][2][B * KP];  // h packed (hi,lo) bf16x2 [dir][buf]
__device__ __nv_bfloat16 g_Whi[2][NPAD * KP];  // Whh permuted [n'][k] hi
__device__ __nv_bfloat16 g_Wlo[2][NPAD * KP];  // lo
__device__ int g_cnt[2][8];                    // group barriers [dir][m-tile]

// ---------------- helpers ----------------
__device__ __forceinline__ void spb(float v, float& hi, float& lo) {
    hi = __bfloat162float(__float2bfloat16(v));
    lo = v - hi;
}
__device__ __forceinline__ uint32_t pack2(float x, float y) {
    __nv_bfloat162 v = __floats2bfloat162_rn(x, y);
    return *reinterpret_cast<uint32_t*>(&v);
}
__device__ __forceinline__ void ldsm4(uint32_t* r, uint32_t addr) {
    asm volatile("ldmatrix.sync.aligned.m8n8.x4.shared.b16 {%0,%1,%2,%3}, [%4];"
        : "=r"(r[0]), "=r"(r[1]), "=r"(r[2]), "=r"(r[3]) : "r"(addr));
}
__device__ __forceinline__ void ldsm2(uint32_t& r0, uint32_t& r1, uint32_t addr) {
    asm volatile("ldmatrix.sync.aligned.m8n8.x2.shared.b16 {%0,%1}, [%2];"
        : "=r"(r0), "=r"(r1) : "r"(addr));
}
__device__ __forceinline__ void mma16(float* c, const uint32_t* a, const uint32_t* b) {
    asm volatile("mma.sync.aligned.m16n8k16.row.col.f32.bf16.bf16.f32 "
        "{%0,%1,%2,%3},{%4,%5,%6,%7},{%8,%9},{%0,%1,%2,%3};"
        : "+f"(c[0]), "+f"(c[1]), "+f"(c[2]), "+f"(c[3])
        : "r"(a[0]), "r"(a[1]), "r"(a[2]), "r"(a[3]), "r"(b[0]), "r"(b[1]));
}
__device__ __forceinline__ uint2 ldcg2(const uint32_t* p) {
    uint2 v;
    asm volatile("ld.global.cg.v2.u32 {%0,%1}, [%2];"
        : "=r"(v.x), "=r"(v.y) : "l"(p));
    return v;
}
__device__ __forceinline__ uint32_t swz(int row, int seg) {
    return (uint32_t)(row * 64 + (((seg + (row >> 1)) & 3) << 4));
}
__device__ __forceinline__ float sigf(float x) {
    return __fdividef(1.f, 1.f + __expf(-x));
}
__device__ __forceinline__ float tanhfast(float x) {
    float xc = fminf(fmaxf(x, -15.f), 15.f);
    float e = __expf(2.f * xc);
    return __fdividef(e - 1.f, e + 1.f);
}

// ---------------- mma chunk, warp tile 32x40, 80B-stride layout (FF gemms) ----------------
__device__ __forceinline__ void mma_chunk80(uint32_t Ab, uint32_t Bb, int lane,
                                            int wm, int wn, float (&acc)[2][5][4]) {
    int r8 = lane & 7, sel = lane >> 3;
    int arow = ((sel & 1) << 3) + r8;
    int akoff = (sel >> 1) << 4;
    uint32_t ah[2][4], al[2][4];
#pragma unroll
    for (int im = 0; im < 2; im++) {
        uint32_t addr = Ab + (uint32_t)((wm + im * 16 + arow) * 80 + akoff);
        ldsm4(ah[im], addr);
        ldsm4(al[im], addr + 32);
    }
    uint32_t bh[5][2], bl[5][2];
    int brow = ((sel >> 1) << 3) + r8;
    int bkoff = (sel & 1) << 4;
#pragma unroll
    for (int j2 = 0; j2 < 2; j2++) {
        uint32_t addr = Bb + (uint32_t)((wn + j2 * 16 + brow) * 80 + bkoff);
        uint32_t t[4];
        ldsm4(t, addr);
        bh[2 * j2][0] = t[0]; bh[2 * j2][1] = t[1];
        bh[2 * j2 + 1][0] = t[2]; bh[2 * j2 + 1][1] = t[3];
        ldsm4(t, addr + 32);
        bl[2 * j2][0] = t[0]; bl[2 * j2][1] = t[1];
        bl[2 * j2 + 1][0] = t[2]; bl[2 * j2 + 1][1] = t[3];
    }
    {
        int row2 = lane & 7;
        int koff2 = ((lane >> 3) & 1) << 4;
        uint32_t addr = Bb + (uint32_t)((wn + 32 + row2) * 80 + koff2);
        ldsm2(bh[4][0], bh[4][1], addr);
        ldsm2(bl[4][0], bl[4][1], addr + 32);
    }
#pragma unroll
    for (int n8 = 0; n8 < 5; n8++)
#pragma unroll
        for (int im = 0; im < 2; im++) {
            mma16(acc[im][n8], ah[im], bh[n8]);
            mma16(acc[im][n8], al[im], bh[n8]);
            mma16(acc[im][n8], ah[im], bl[n8]);
        }
}

// ---------------- B-fragment + mma for the swizzled 64B layout (lstm) ----------------
__device__ __forceinline__ void mma_bpart64(uint32_t Bb, int lane, int wn,
                                            const uint32_t (&ah)[2][4],
                                            const uint32_t (&al)[2][4],
                                            float (&acc)[2][5][4]) {
    int r8 = lane & 7, sel = lane >> 3;
    uint32_t bh[5][2], bl[5][2];
    int brow = ((sel >> 1) << 3) + r8;
    int bkseg = sel & 1;
#pragma unroll
    for (int j2 = 0; j2 < 2; j2++) {
        int row = wn + j2 * 16 + brow;
        uint32_t t[4];
        ldsm4(t, Bb + swz(row, bkseg));
        bh[2 * j2][0] = t[0]; bh[2 * j2][1] = t[1];
        bh[2 * j2 + 1][0] = t[2]; bh[2 * j2 + 1][1] = t[3];
        ldsm4(t, Bb + swz(row, bkseg + 2));
        bl[2 * j2][0] = t[0]; bl[2 * j2][1] = t[1];
        bl[2 * j2 + 1][0] = t[2]; bl[2 * j2 + 1][1] = t[3];
    }
    {
        int row = wn + 32 + (lane & 7);
        int seg = (lane >> 3) & 1;
        ldsm2(bh[4][0], bh[4][1], Bb + swz(row, seg));
        ldsm2(bl[4][0], bl[4][1], Bb + swz(row, seg + 2));
    }
#pragma unroll
    for (int n8 = 0; n8 < 5; n8++)
#pragma unroll
        for (int im = 0; im < 2; im++) {
            mma16(acc[im][n8], ah[im], bh[n8]);
            mma16(acc[im][n8], al[im], bh[n8]);
            mma16(acc[im][n8], ah[im], bl[n8]);
        }
}

// ---------------- merged prologue: zero state + counters + Whh prep ----------------
__global__ void prologue_kernel(const float* __restrict__ Wf,
                                const float* __restrict__ Wb) {
    int i = blockIdx.x * blockDim.x + threadIdx.x;
    if (i < 2 * 2 * B * KP) (&g_hpk[0][0][0])[i] = 0u;
    if (i < 16) (&g_cnt[0][0])[i] = 0;
    if (i < 2 * NPAD * KP) {
        int dir = i / (NPAD * KP);
        int r = i - dir * (NPAD * KP);
        int np = r / KP, k = r - np * KP;
        float v = 0.f;
        if (np < G4 && k < H) {
            const float* W = dir ? Wb : Wf;
            v = W[(size_t)((np & 3) * H + (np >> 2)) * H + k];
        }
        float hi, lo; spb(v, hi, lo);
        g_Whi[dir][r] = __float2bfloat16(hi);
        g_Wlo[dir][r] = __float2bfloat16(lo);
    }
}

__global__ void embed_kernel(const int* __restrict__ word,
                             const int* __restrict__ sem,
                             const float* __restrict__ wt,
                             const float* __restrict__ st) {
    int b = blockIdx.x;
    int e = threadIdx.x;
    __shared__ int sidx[L];
    __shared__ int widx;
    if (e < L) sidx[e] = sem[b * L + e];
    if (e == 0) widx = word[b];
    __syncthreads();
    if (e < E) {
        float acc = 0.f;
#pragma unroll
        for (int l = 0; l < L; l++) acc += st[sidx[l] * E + e];
        g_ag[b * E + e] = acc * (1.f / (float)L);
        g_w [b * E + e] = wt[widx * E + e];
    }
}

// ---------------- feed-forward gemm body (4-deep ring, sync per 2 chunks) ----------------
__device__ __forceinline__ void gemm_body(
    unsigned char* smraw,
    const float* A, int lda, const float* W, int ldw, int imap,
    const float* b1, const float* b2, float* C,
    int M, int N, int K, int dorelu, int bx, int by)
{
    uint32_t sbase = (uint32_t)__cvta_generic_to_shared(smraw);
    uint32_t* smw = (uint32_t*)smraw;

    int tid = threadIdx.x, lane = tid & 31, wid = tid >> 5;
    int g = lane >> 2, t4 = lane & 3;
    int wm = (wid >> 2) * 32, wn = (wid & 3) * 40;
    int m0 = by * 128, n0 = bx * 160;

    float acc[2][5][4];
#pragma unroll
    for (int a = 0; a < 2; a++)
#pragma unroll
        for (int b = 0; b < 5; b++)
#pragma unroll
            for (int c = 0; c < 4; c++) acc[a][b][c] = 0.f;

    int NC = (K + 15) / 16;
    int NG = (NC + 1) / 2;
    float4 ra[2], rb[2][2];

    auto loadregs = [&](int kc, int sl) {
        int k0 = kc * 16;
        {
            int row = tid >> 2, q4 = tid & 3;
            int gm = m0 + row, kk = k0 + q4 * 4;
            float4 v = make_float4(0.f, 0.f, 0.f, 0.f);
            if (gm < M) {
                const float* ap = A + (size_t)gm * lda;
                if (kk + 3 < K) v = *(const float4*)(ap + kk);
                else {
                    if (kk + 0 < K) v.x = ap[kk + 0];
                    if (kk + 1 < K) v.y = ap[kk + 1];
                    if (kk + 2 < K) v.z = ap[kk + 2];
                    if (kk + 3 < K) v.w = ap[kk + 3];
                }
            }
            ra[sl] = v;
        }
#pragma unroll
        for (int q = 0; q < 2; q++) {
            int p = tid + q * 512;
            float4 v = make_float4(0.f, 0.f, 0.f, 0.f);
            if (p < 640) {
                int row = p >> 2, q4 = p & 3;
                int nr = n0 + row, kk = k0 + q4 * 4;
                if (nr < N) {
                    int grow = imap ? ((nr & 3) * H + (nr >> 2)) : nr;
                    const float* wp = W + (size_t)grow * ldw;
                    if (kk + 3 < K) v = *(const float4*)(wp + kk);
                    else {
                        if (kk + 0 < K) v.x = wp[kk + 0];
                        if (kk + 1 < K) v.y = wp[kk + 1];
                        if (kk + 2 < K) v.z = wp[kk + 2];
                        if (kk + 3 < K) v.w = wp[kk + 3];
                    }
                }
            }
            rb[sl][q] = v;
        }
    };
    auto storeregs = [&](int sl, int buf) {
        uint32_t* Aw = smw + buf * (BUFB / 4);
        uint32_t* Bw = Aw + ABYTES / 4;
        {
            int row = tid >> 2, q4 = tid & 3;
            float h0, l0, h1, l1, h2, l2, h3, l3;
            spb(ra[sl].x, h0, l0); spb(ra[sl].y, h1, l1);
            spb(ra[sl].z, h2, l2); spb(ra[sl].w, h3, l3);
            Aw[row * 20 + q4 * 2]     = pack2(h0, h1);
            Aw[row * 20 + q4 * 2 + 1] = pack2(h2, h3);
            Aw[row * 20 + 8 + q4 * 2]     = pack2(l0, l1);
            Aw[row * 20 + 8 + q4 * 2 + 1] = pack2(l2, l3);
        }
#pragma unroll
        for (int q = 0; q < 2; q++) {
            int p = tid + q * 512;
            if (p < 640) {
                int row = p >> 2, q4 = p & 3;
                float h0, l0, h1, l1, h2, l2, h3, l3;
                spb(rb[sl][q].x, h0, l0); spb(rb[sl][q].y, h1, l1);
                spb(rb[sl][q].z, h2, l2); spb(rb[sl][q].w, h3, l3);
                Bw[row * 20 + q4 * 2]     = pack2(h0, h1);
                Bw[row * 20 + q4 * 2 + 1] = pack2(h2, h3);
                Bw[row * 20 + 8 + q4 * 2]     = pack2(l0, l1);
                Bw[row * 20 + 8 + q4 * 2 + 1] = pack2(l2, l3);
            }
        }
    };

    loadregs(0, 0);
    if (1 < NC) loadregs(1, 1);
    storeregs(0, 0);
    if (1 < NC) storeregs(1, 1);
    __syncthreads();
    for (int gg = 0; gg < NG; gg++) {
        int base2 = 2 * gg;
        if (gg + 1 < NG) {
            loadregs(base2 + 2, 0);
            if (base2 + 3 < NC) loadregs(base2 + 3, 1);
        }
        mma_chunk80(sbase + (uint32_t)((base2 & 3) * BUFB),
                    sbase + (uint32_t)((base2 & 3) * BUFB) + ABYTES, lane, wm, wn, acc);
        if (base2 + 1 < NC)
            mma_chunk80(sbase + (uint32_t)(((base2 + 1) & 3) * BUFB),
                        sbase + (uint32_t)(((base2 + 1) & 3) * BUFB) + ABYTES, lane, wm, wn, acc);
        if (gg + 1 < NG) {
            storeregs(0, (base2 + 2) & 3);
            if (base2 + 3 < NC) storeregs(1, (base2 + 3) & 3);
        }
        __syncthreads();
    }

#pragma unroll
    for (int in8 = 0; in8 < 5; in8++) {
        int n_g = n0 + wn + in8 * 8 + 2 * t4;
        float bv0 = 0.f, bv1 = 0.f;
        if (n_g < N) {
            int i0 = imap ? ((n_g & 3) * H + (n_g >> 2)) : n_g;
            if (b1) bv0 += b1[i0];
            if (b2) bv0 += b2[i0];
        }
        if (n_g + 1 < N) {
            int i1 = imap ? (((n_g + 1) & 3) * H + ((n_g + 1) >> 2)) : (n_g + 1);
            if (b1) bv1 += b1[i1];
            if (b2) bv1 += b2[i1];
        }
#pragma unroll
        for (int im = 0; im < 2; im++) {
            int r0 = m0 + wm + im * 16 + g;
            if (r0 < M) {
                if (n_g < N) {
                    float v = acc[im][in8][0] + bv0;
                    if (dorelu) v = fmaxf(v, 0.f);
                    C[(size_t)r0 * N + n_g] = v;
                }
                if (n_g + 1 < N) {
                    float v = acc[im][in8][1] + bv1;
                    if (dorelu) v = fmaxf(v, 0.f);
                    C[(size_t)r0 * N + n_g + 1] = v;
                }
            }
            int r1 = r0 + 8;
            if (r1 < M) {
                if (n_g < N) {
                    float v = acc[im][in8][2] + bv0;
                    if (dorelu) v = fmaxf(v, 0.f);
                    C[(size_t)r1 * N + n_g] = v;
                }
                if (n_g + 1 < N) {
                    float v = acc[im][in8][3] + bv1;
                    if (dorelu) v = fmaxf(v, 0.f);
                    C[(size_t)r1 * N + n_g + 1] = v;
                }
            }
        }
    }
}

// ---------------- merged feed-forward launch ----------------
__global__ void __launch_bounds__(512) gemm_ff(
    const float* Wb_, const float* bb_, const float* st,
    const float* Wih_f, const float* Wih_b,
    const float* bih_f, const float* bhh_f,
    const float* bih_b, const float* bhh_b,
    float* vg_out, float* psf, float* psb, float* pwf, float* pwb)
{
    extern __shared__ __align__(16) unsigned char smdyn[];
    int bid = blockIdx.x;
    if (bid < 16) {
        gemm_body(smdyn, g_ag, E, Wb_, E, 0, bb_, nullptr, vg_out,
                  B, E, E, 1, bid & 1, bid >> 1);
    } else if (bid < 160) {
        int r = bid - 16;
        gemm_body(smdyn, st, E, Wih_f + E, 2 * E, 1, bih_f, bhh_f, psf,
                  VS, G4, E, 0, r & 7, r >> 3);
    } else if (bid < 304) {
        int r = bid - 160;
        gemm_body(smdyn, st, E, Wih_b + E, 2 * E, 1, bih_b, bhh_b, psb,
                  VS, G4, E, 0, r & 7, r >> 3);
    } else if (bid < 368) {
        int r = bid - 304;
        gemm_body(smdyn, g_w, E, Wih_f, 2 * E, 1, nullptr, nullptr, pwf,
                  B, G4, E, 0, r & 7, r >> 3);
    } else {
        int r = bid - 368;
        gemm_body(smdyn, g_w, E, Wih_b, 2 * E, 1, nullptr, nullptr, pwb,
                  B, G4, E, 0, r & 7, r >> 3);
    }
}

__global__ void __launch_bounds__(512) gemm_v(
    const float* Wa, const float* ba, float* Vout)
{
    extern __shared__ __align__(16) unsigned char smdyn[];
    gemm_body(smdyn, g_Vh, 2 * H, Wa, 2 * H, 0, ba, nullptr, Vout,
              BL, H, 2 * H, 1, blockIdx.x, blockIdx.y);
}

// ---------------- persistent LSTM: sync-free k-loop, A direct from L2 ----------------
__global__ void __launch_bounds__(512) lstm_persistent(const int* __restrict__ sem) {
    extern __shared__ __align__(16) unsigned char smraw[];
    uint32_t sbase = (uint32_t)__cvta_generic_to_shared(smraw);
    const int dir = blockIdx.z, mt = blockIdx.y, nt = blockIdx.x;
    const int m0 = mt * 128, n0 = nt * 160;

    int tid = threadIdx.x, lane = tid & 31, wid = tid >> 5;
    int g = lane >> 2, t4 = lane & 3;
    int wm = (wid >> 2) * 32, wn = (wid & 3) * 40;
    int parity = lane & 1;

    uint32_t Bbase = sbase;   // 19 chunks x 10240, B only

    // load Whh tile into smem once (swizzled)
    {
        const __nv_bfloat16* Whi = g_Whi[dir];
        const __nv_bfloat16* Wlo = g_Wlo[dir];
        for (int p = tid; p < 19 * 640; p += 512) {
            int kc = p / 640, r = p - kc * 640;
            int row = r >> 2, seg = r & 3;
            int plane = seg >> 1, half = seg & 1;
            const __nv_bfloat16* src = plane ? Wlo : Whi;
            uint4 v = *(const uint4*)(src + (size_t)(n0 + row) * KP + kc * 16 + half * 8);
            *(uint4*)(smraw + kc * 10240 + swz(row, seg)) = v;
        }
    }
    __syncthreads();

    const float* sproj = g_sproj[dir];
    const float* wproj = g_wproj[dir];

    float cst[2][5];
#pragma unroll
    for (int a = 0; a < 2; a++)
#pragma unroll
        for (int b = 0; b < 5; b++) cst[a][b] = 0.f;

    int r8l = lane >> 2;
    int kpl = (lane & 3) * 2;

    for (int s = 0; s < L; s++) {
        float acc[2][5][4];
#pragma unroll
        for (int a = 0; a < 2; a++)
#pragma unroll
            for (int b = 0; b < 5; b++)
#pragma unroll
                for (int c = 0; c < 4; c++) acc[a][b][c] = 0.f;

        if (s > 0) {
            const uint32_t* Arow = g_hpk[dir][(s - 1) & 1] + (size_t)m0 * KP;
            const uint32_t* p0base0 = Arow + (size_t)(wm + r8l) * KP + kpl;
            const uint32_t* p0base1 = Arow + (size_t)(wm + 16 + r8l) * KP + kpl;
            uint2 ub[2][8];
            auto ldA = [&](int kc, int buf) {
                const uint32_t* p0 = p0base0 + kc * 16;
                ub[buf][0] = ldcg2(p0);
                ub[buf][1] = ldcg2(p0 + 8 * KP);
                ub[buf][2] = ldcg2(p0 + 8);
                ub[buf][3] = ldcg2(p0 + 8 * KP + 8);
                const uint32_t* p1 = p0base1 + kc * 16;
                ub[buf][4] = ldcg2(p1);
                ub[buf][5] = ldcg2(p1 + 8 * KP);
                ub[buf][6] = ldcg2(p1 + 8);
                ub[buf][7] = ldcg2(p1 + 8 * KP + 8);
            };
            ldA(0, 0);
            for (int kc = 0; kc < 19; kc++) {
                int cur = kc & 1;
                if (kc + 1 < 19) ldA(kc + 1, cur ^ 1);
                uint32_t ah[2][4], al[2][4];
#pragma unroll
                for (int im = 0; im < 2; im++)
#pragma unroll
                    for (int q = 0; q < 4; q++) {
                        uint2 u = ub[cur][im * 4 + q];
                        ah[im][q] = __byte_perm(u.x, u.y, 0x5410);
                        al[im][q] = __byte_perm(u.x, u.y, 0x7632);
                    }
                mma_bpart64(Bbase + (uint32_t)(kc * 10240), lane, wn, ah, al, acc);
            }
        }

        // epilogue
        int t = dir ? (L - 1 - s) : s;
        uint32_t* Hpk = g_hpk[dir][s & 1];
#pragma unroll
        for (int im = 0; im < 2; im++) {
            int rowl = wm + im * 16 + g + (parity ? 8 : 0);
            int b = m0 + rowl;
            int idx = sem[b * L + t];
            const float* sp = sproj + (size_t)idx * G4;
            const float* wp = wproj + (size_t)b * G4;
            float wmul = (idx != 0) ? 1.f : 0.f;
#pragma unroll
            for (int n8 = 0; n8 < 5; n8++) {
                float c0 = acc[im][n8][0], c1 = acc[im][n8][1];
                float c2 = acc[im][n8][2], c3 = acc[im][n8][3];
                float s1 = parity ? c0 : c2;
                float s2 = parity ? c1 : c3;
                float r1 = __shfl_xor_sync(0xffffffffu, s1, 1);
                float r2 = __shfl_xor_sync(0xffffffffu, s2, 1);
                float gi, gf, gg2, go;
                if (!parity) { gi = c0; gf = c1; gg2 = r1; go = r2; }
                else         { gi = r1; gf = r2; gg2 = c2; go = c3; }
                int j = (n0 + wn + n8 * 8 + 2 * t4) >> 2;
                if (j < H) {
                    float4 spv = *(const float4*)(sp + 4 * j);
                    float4 wpv = *(const float4*)(wp + 4 * j);
                    gi  += spv.x + wmul * wpv.x;
                    gf  += spv.y + wmul * wpv.y;
                    gg2 += spv.z + wmul * wpv.z;
                    go  += spv.w + wmul * wpv.w;
                    float ig = sigf(gi);
                    float fg = sigf(gf);
                    float gt = tanhfast(gg2);
                    float og = sigf(go);
                    float cn = fg * cst[im][n8] + ig * gt;
                    cst[im][n8] = cn;
                    float h = og * tanhfast(cn);
                    g_Vh[(size_t)(b * L + t) * (2 * H) + dir * H + j] = h;
                    float hh, hl; spb(h, hh, hl);
                    Hpk[(size_t)b * KP + j] = pack2(hh, hl);
                }
            }
        }

        // group barrier: release/acquire
        if (s < L - 1) {
            __syncthreads();
            if (tid == 0) {
                int* cp = &g_cnt[dir][mt];
                asm volatile("red.release.gpu.global.add.s32 [%0], 1;"
                             :: "l"(cp) : "memory");
                int target = 8 * (s + 1);
                int v;
                while (true) {
                    asm volatile("ld.acquire.gpu.global.b32 %0, [%1];"
                                 : "=r"(v) : "l"(cp) : "memory");
                    if (v >= target) break;
                    __nanosleep(64);
                }
            }
            __syncthreads();
        }
    }
}

// ---------------- launch ----------------
extern "C" void kernel_launch(void* const* d_in, const int* in_sizes, int n_in,
                              void* d_out, int out_size) {
    const int*   word  = (const int*)d_in[0];
    const int*   sem   = (const int*)d_in[1];
    const float* wt    = (const float*)d_in[2];
    const float* st    = (const float*)d_in[3];
    const float* Wih_f = (const float*)d_in[4];
    const float* Whh_f = (const float*)d_in[5];
    const float* bih_f = (const float*)d_in[6];
    const float* bhh_f = (const float*)d_in[7];
    const float* Wih_b = (const float*)d_in[8];
    const float* Whh_b = (const float*)d_in[9];
    const float* bih_b = (const float*)d_in[10];
    const float* bhh_b = (const float*)d_in[11];
    const float* Wa    = (const float*)d_in[12];
    const float* ba    = (const float*)d_in[13];
    const float* Wb    = (const float*)d_in[14];
    const float* bb    = (const float*)d_in[15];

    float* out    = (float*)d_out;
    float* Vout   = out;
    float* vg_out = out + (size_t)B * L * H;

    void* p;
    float *psf, *psb, *pwf, *pwb;
    cudaGetSymbolAddress(&p, g_sproj); psf = (float*)p; psb = psf + (size_t)VS * G4;
    cudaGetSymbolAddress(&p, g_wproj); pwf = (float*)p; pwb = pwf + (size_t)B * G4;

    cudaFuncSetAttribute(lstm_persistent,
                         cudaFuncAttributeMaxDynamicSharedMemorySize, PSMEM);
    cudaFuncSetAttribute(gemm_ff,
                         cudaFuncAttributeMaxDynamicSharedMemorySize, FFSMEM);
    cudaFuncSetAttribute(gemm_v,
                         cudaFuncAttributeMaxDynamicSharedMemorySize, FFSMEM);

    prologue_kernel<<<(2 * NPAD * KP + 255) / 256, 256>>>(Whh_f, Whh_b);
    embed_kernel<<<B, 320>>>(word, sem, wt, st);

    gemm_ff<<<432, 512, FFSMEM>>>(Wb, bb, st, Wih_f, Wih_b,
                                  bih_f, bhh_f, bih_b, bhh_b,
                                  vg_out, psf, psb, pwf, pwb);

    lstm_persistent<<<dim3(8, 8, 2), 512, PSMEM>>>(sem);

    gemm_v<<<dim3(2, 144), 512, FFSMEM>>>(Wa, ba, Vout);
}